// round 3
// baseline (speedup 1.0000x reference)
#include <cuda_runtime.h>
#include <math.h>

// ---------------- problem constants ----------------
#define BB 4
#define LL 4096
#define EE 512
#define FF 2049
#define HH 8
#define DD 64
#define FFTM 2048          // half-size complex FFT length

// ---------------- scratch (device globals; allocation-free) ----------------
__device__ float g_xn[BB * LL * EE];       // layernormed x       [B][L][E]
__device__ float g_xt[BB * EE * LL];       // transposed          [B][E][L] (reused for irfft output)
__device__ float g_xr[BB * FF * EE];       // rfft real           [B][F][E]
__device__ float g_xi[BB * FF * EE];       // rfft imag
__device__ float g_Qr[BB * FF * EE];
__device__ float g_Qi[BB * FF * EE];
__device__ float g_Kr[BB * FF * EE];
__device__ float g_Ki[BB * FF * EE];
__device__ float g_Vr[BB * FF * EE];
__device__ float g_Vi[BB * FF * EE];
__device__ float g_Or[BB * FF * EE];       // attention out real  [B][F][E]
__device__ float g_Oi[BB * FF * EE];
__device__ float g_y [BB * LL * EE];       // irfft result        [B][L][E]

// ---------------- LayerNorm ----------------
__global__ void ln_kernel(const float* __restrict__ x,
                          const float* __restrict__ gam,
                          const float* __restrict__ bet)
{
    __shared__ float sa[8], sb[8];
    int row = blockIdx.x;                  // b*L + l
    const float* xr = x + (size_t)row * EE;
    float* o = g_xn + (size_t)row * EE;
    int t = threadIdx.x;                   // 256 threads
    float v0 = xr[t], v1 = xr[t + 256];
    float s = v0 + v1, s2 = v0 * v0 + v1 * v1;
#pragma unroll
    for (int off = 16; off; off >>= 1) {
        s  += __shfl_xor_sync(0xffffffffu, s,  off);
        s2 += __shfl_xor_sync(0xffffffffu, s2, off);
    }
    if ((t & 31) == 0) { sa[t >> 5] = s; sb[t >> 5] = s2; }
    __syncthreads();
    s = 0.f; s2 = 0.f;
#pragma unroll
    for (int i = 0; i < 8; i++) { s += sa[i]; s2 += sb[i]; }
    float mean = s * (1.0f / EE);
    float var  = s2 * (1.0f / EE) - mean * mean;
    float rs   = rsqrtf(var + 1e-5f);
    o[t]       = (v0 - mean) * rs * gam[t]       + bet[t];
    o[t + 256] = (v1 - mean) * rs * gam[t + 256] + bet[t + 256];
}

// ---------------- transposes ----------------
// g_xn [B][L][E] -> g_xt [B][E][L].  grid (E/32, L/32, B), block (32,8)
__global__ void transpose_LE_to_EL()
{
    __shared__ float tile[32][33];
    int b  = blockIdx.z;
    int e0 = blockIdx.x * 32;
    int l0 = blockIdx.y * 32;
    const float* s = g_xn + ((size_t)b * LL + l0) * EE + e0;
    for (int rr = threadIdx.y; rr < 32; rr += 8)
        tile[rr][threadIdx.x] = s[(size_t)rr * EE + threadIdx.x];
    __syncthreads();
    float* d = g_xt + ((size_t)b * EE + e0) * LL + l0;
    for (int rr = threadIdx.y; rr < 32; rr += 8)
        d[(size_t)rr * LL + threadIdx.x] = tile[threadIdx.x][rr];
}

// g_xt [B][E][L] -> g_y [B][L][E].  grid (L/32, E/32, B), block (32,8)
__global__ void transpose_EL_to_LE()
{
    __shared__ float tile[32][33];
    int b  = blockIdx.z;
    int l0 = blockIdx.x * 32;
    int e0 = blockIdx.y * 32;
    const float* s = g_xt + ((size_t)b * EE + e0) * LL + l0;
    for (int rr = threadIdx.y; rr < 32; rr += 8)
        tile[rr][threadIdx.x] = s[(size_t)rr * LL + threadIdx.x];
    __syncthreads();
    float* d = g_y + ((size_t)b * LL + l0) * EE + e0;
    for (int rr = threadIdx.y; rr < 32; rr += 8)
        d[(size_t)rr * EE + threadIdx.x] = tile[threadIdx.x][rr];
}

// ---------------- Stockham FFT (complex, length 2048, 256 threads) ----------------
// tw[j] = exp(sign * 2*pi*i * j / 2048), j in [0,1024)
__device__ __forceinline__ float2* fft_stockham2048(float2* src, float2* dst,
                                                    const float2* __restrict__ tw, int t)
{
#pragma unroll 1
    for (int stage = 0; stage < 11; stage++) {
        int s = 1 << stage;
#pragma unroll
        for (int i = 0; i < 4; i++) {
            int j = t + (i << 8);                 // 0..1023
            int p = j >> stage;
            int q = j & (s - 1);
            float2 u = src[q + (p << stage)];
            float2 v = src[q + ((p + (1024 >> stage)) << stage)];
            float2 ss = make_float2(u.x + v.x, u.y + v.y);
            float2 dd = make_float2(u.x - v.x, u.y - v.y);
            float2 w  = tw[p << stage];
            int od = q + (p << (stage + 1));
            dst[od]     = ss;
            dst[od + s] = make_float2(dd.x * w.x - dd.y * w.y,
                                      dd.x * w.y + dd.y * w.x);
        }
        __syncthreads();
        float2* tmp = src; src = dst; dst = tmp;
    }
    return src;   // after odd number of swaps this is the last-written buffer
}

// rfft(4096, ortho) per (b,e) series via complex-2048 FFT.  grid B*E, block 256
__global__ void rfft_kernel()
{
    __shared__ float2 bufA[FFTM], bufB[FFTM];
    __shared__ float2 tw[1024];
    int t  = threadIdx.x;
    int be = blockIdx.x;                 // b*E + e
    int b  = be >> 9, e = be & 511;

    const float2* src = (const float2*)(g_xt + (size_t)be * LL);   // z[n] = x[2n] + i x[2n+1]
#pragma unroll
    for (int i = 0; i < 8; i++) bufA[t + (i << 8)] = src[t + (i << 8)];
#pragma unroll
    for (int i = 0; i < 4; i++) {
        int p = t + (i << 8);
        float sn, cs; sincospif(-(float)p * (1.0f / 1024.0f), &sn, &cs);  // e^{-2pi i p/2048}
        tw[p] = make_float2(cs, sn);
    }
    __syncthreads();
    float2* Z = fft_stockham2048(bufA, bufB, tw, t);

    const float scale = 1.0f / 64.0f;    // ortho: 1/sqrt(4096)
    for (int k = t; k <= FFTM; k += 256) {
        float2 zk = Z[k & (FFTM - 1)];
        float2 zm = Z[(FFTM - k) & (FFTM - 1)];
        float Er  = 0.5f * (zk.x + zm.x);
        float Eii = 0.5f * (zk.y - zm.y);
        float Or0 = 0.5f * (zk.x - zm.x);
        float Oi0 = 0.5f * (zk.y + zm.y);
        float sn, cs; sincospif(-(float)k * (1.0f / 2048.0f), &sn, &cs);  // e^{-2pi i k/4096}
        float ux = cs * Or0 - sn * Oi0;
        float uy = cs * Oi0 + sn * Or0;
        size_t g = ((size_t)b * FF + k) * EE + e;
        g_xr[g] = (Er  + uy) * scale;
        g_xi[g] = (Eii - ux) * scale;
    }
}

// irfft(4096, ortho) per (b,e); reads g_Or/g_Oi [B][F][E], writes g_xt as [B][E][L]
__global__ void irfft_kernel()
{
    __shared__ float2 bufA[FFTM], bufB[FFTM];
    __shared__ float2 tw[1024];
    int t  = threadIdx.x;
    int be = blockIdx.x;
    int b  = be >> 9, e = be & 511;

#pragma unroll
    for (int i = 0; i < 4; i++) {
        int p = t + (i << 8);
        float sn, cs; sincospif((float)p * (1.0f / 1024.0f), &sn, &cs);   // e^{+2pi i p/2048}
        tw[p] = make_float2(cs, sn);
    }
    // build Z[k] from half-spectrum (imag of DC and Nyquist ignored, per c2r)
    for (int k = t; k < FFTM; k += 256) {
        size_t gk = ((size_t)b * FF + k) * EE + e;
        size_t gm = ((size_t)b * FF + (FFTM - k)) * EE + e;
        float Xr_k = g_Or[gk];
        float Xi_k = (k == 0) ? 0.0f : g_Oi[gk];
        float Xr_m = g_Or[gm];
        float Xi_m = (k == 0) ? 0.0f : g_Oi[gm];   // k==0 -> mirror is Nyquist (imag dropped)
        float Er  = 0.5f * (Xr_k + Xr_m);
        float Ei  = 0.5f * (Xi_k - Xi_m);
        float Or0 = 0.5f * (Xr_k - Xr_m);
        float Oi0 = 0.5f * (Xi_k + Xi_m);
        float sn, cs; sincospif((float)k * (1.0f / 2048.0f), &sn, &cs);   // e^{+2pi i k/4096}
        float ux = cs * Or0 - sn * Oi0;
        float uy = cs * Oi0 + sn * Or0;
        bufA[k] = make_float2(Er - uy, Ei + ux);   // Z = E + i*O
    }
    __syncthreads();
    float2* w = fft_stockham2048(bufA, bufB, tw, t);  // unnormalized inverse (e^{+})

    float2* out = (float2*)(g_xt + (size_t)be * LL);
    const float sc = 1.0f / 32.0f;                 // sqrt(4096)/2048
#pragma unroll
    for (int i = 0; i < 8; i++) {
        int n = t + (i << 8);
        float2 z = w[n];
        out[n] = make_float2(z.x * sc, z.y * sc);  // x[2n], x[2n+1]
    }
}

// ---------------- NT GEMM: C[M,512] = A[M,512] * W[512,512]^T (+bias) ----------------
__global__ void __launch_bounds__(256) gemm_nt(const float* __restrict__ A,
                                               const float* __restrict__ W,
                                               const float* __restrict__ bias,
                                               float* __restrict__ C, int M)
{
    __shared__ float As[16][65];
    __shared__ float Bs[16][65];
    int m0 = blockIdx.x * 64, n0 = blockIdx.y * 64;
    int t = threadIdx.x, tx = t & 15, ty = t >> 4;
    int lm = t >> 2;             // 0..63
    int lk = (t & 3) * 4;        // 0,4,8,12
    float acc[4][4] = {};

    for (int k0 = 0; k0 < 512; k0 += 16) {
        float4 a4 = make_float4(0.f, 0.f, 0.f, 0.f);
        if (m0 + lm < M)
            a4 = *(const float4*)&A[(size_t)(m0 + lm) * 512 + k0 + lk];
        float4 b4 = *(const float4*)&W[(size_t)(n0 + lm) * 512 + k0 + lk];
        __syncthreads();
        As[lk + 0][lm] = a4.x; As[lk + 1][lm] = a4.y; As[lk + 2][lm] = a4.z; As[lk + 3][lm] = a4.w;
        Bs[lk + 0][lm] = b4.x; Bs[lk + 1][lm] = b4.y; Bs[lk + 2][lm] = b4.z; Bs[lk + 3][lm] = b4.w;
        __syncthreads();
#pragma unroll
        for (int kk = 0; kk < 16; kk++) {
            float a[4], bb[4];
#pragma unroll
            for (int i = 0; i < 4; i++) a[i] = As[kk][ty * 4 + i];
#pragma unroll
            for (int j = 0; j < 4; j++) bb[j] = Bs[kk][tx * 4 + j];
#pragma unroll
            for (int i = 0; i < 4; i++)
#pragma unroll
                for (int j = 0; j < 4; j++) acc[i][j] += a[i] * bb[j];
        }
    }
    float bv[4] = {0.f, 0.f, 0.f, 0.f};
    if (bias)
#pragma unroll
        for (int j = 0; j < 4; j++) bv[j] = bias[n0 + tx * 4 + j];
#pragma unroll
    for (int i = 0; i < 4; i++) {
        int m = m0 + ty * 4 + i;
        if (m < M) {
#pragma unroll
            for (int j = 0; j < 4; j++)
                C[(size_t)m * 512 + n0 + tx * 4 + j] = acc[i][j] + bv[j];
        }
    }
}

// ---------------- fused flash attention over frequency bins ----------------
// grid: (33 q-tiles, B*H).  block 256.  dyn smem = 5 * 64*65 * 4 = 83200 B
#define ATTN_SMEM (5 * 64 * 65 * 4)
__global__ void __launch_bounds__(256, 2) attn_kernel(
    const float* __restrict__ Qr, const float* __restrict__ Qi,
    const float* __restrict__ Kr, const float* __restrict__ Ki,
    const float* __restrict__ Vr, const float* __restrict__ Vi,
    float* __restrict__ Outr, float* __restrict__ Outi)
{
    extern __shared__ float sm[];
    float* sQr = sm;                    // [d][q]  64x65
    float* sQi = sQr + 64 * 65;
    float* sKr = sQi + 64 * 65;         // K: [d][f] ; reused for V: [f][d]
    float* sKi = sKr + 64 * 65;
    float* sP  = sKi + 64 * 65;         // [q][k]  64x65

    int b = blockIdx.y >> 3, h = blockIdx.y & 7;
    int q0 = blockIdx.x * 64;
    int t = threadIdx.x, tx = t & 15, ty = t >> 4;
    const size_t basebh = (size_t)b * FF * EE + h * DD;

    // load Q tiles transposed, pre-scaled by d^-1/2
    for (int idx = t; idx < 4096; idx += 256) {
        int q = idx >> 6, d = idx & 63;
        int qf = q0 + q;
        float vr = 0.f, vi = 0.f;
        if (qf < FF) {
            size_t g = basebh + (size_t)qf * EE + d;
            vr = Qr[g] * 0.125f; vi = Qi[g] * 0.125f;
        }
        sQr[d * 65 + q] = vr;
        sQi[d * 65 + q] = vi;
    }

    float m_[4], l_[4], oR[4][4] = {}, oI[4][4] = {};
#pragma unroll
    for (int i = 0; i < 4; i++) { m_[i] = -1e30f; l_[i] = 0.f; }

    for (int k0 = 0; k0 < 2112; k0 += 64) {
        // K tile: [d][f]
        for (int idx = t; idx < 4096; idx += 256) {
            int f = idx >> 6, d = idx & 63;
            int kf = k0 + f;
            float vr = 0.f, vi = 0.f;
            if (kf < FF) {
                size_t g = basebh + (size_t)kf * EE + d;
                vr = Kr[g]; vi = Ki[g];
            }
            sKr[d * 65 + f] = vr;
            sKi[d * 65 + f] = vi;
        }
        __syncthreads();

        // S = Qr.Kr^T + Qi.Ki^T
        float acc[4][4] = {};
#pragma unroll 4
        for (int kk = 0; kk < 64; kk++) {
            float ar[4], ai[4], br[4], bi[4];
#pragma unroll
            for (int i = 0; i < 4; i++) { ar[i] = sQr[kk * 65 + ty * 4 + i]; ai[i] = sQi[kk * 65 + ty * 4 + i]; }
#pragma unroll
            for (int j = 0; j < 4; j++) { br[j] = sKr[kk * 65 + tx * 4 + j]; bi[j] = sKi[kk * 65 + tx * 4 + j]; }
#pragma unroll
            for (int i = 0; i < 4; i++)
#pragma unroll
                for (int j = 0; j < 4; j++)
                    acc[i][j] += ar[i] * br[j] + ai[i] * bi[j];
        }
        // mask invalid keys
#pragma unroll
        for (int j = 0; j < 4; j++)
            if (k0 + tx * 4 + j >= FF) {
#pragma unroll
                for (int i = 0; i < 4; i++) acc[i][j] = -1e30f;
            }
        // online softmax (16 lanes with equal ty share rows; xor 1,2,4,8)
        float alpha[4];
#pragma unroll
        for (int i = 0; i < 4; i++) {
            float rm = fmaxf(fmaxf(acc[i][0], acc[i][1]), fmaxf(acc[i][2], acc[i][3]));
#pragma unroll
            for (int off = 1; off < 16; off <<= 1)
                rm = fmaxf(rm, __shfl_xor_sync(0xffffffffu, rm, off));
            float mn = fmaxf(m_[i], rm);
            alpha[i] = __expf(m_[i] - mn);
            m_[i] = mn;
            float rs = 0.f;
#pragma unroll
            for (int j = 0; j < 4; j++) { float p = __expf(acc[i][j] - mn); acc[i][j] = p; rs += p; }
#pragma unroll
            for (int off = 1; off < 16; off <<= 1)
                rs += __shfl_xor_sync(0xffffffffu, rs, off);
            l_[i] = l_[i] * alpha[i] + rs;
#pragma unroll
            for (int j = 0; j < 4; j++) { oR[i][j] *= alpha[i]; oI[i][j] *= alpha[i]; }
        }
        __syncthreads();   // done reading K tile

        // store P, load V tiles [f][d] into the K buffers
#pragma unroll
        for (int i = 0; i < 4; i++)
#pragma unroll
            for (int j = 0; j < 4; j++)
                sP[(ty * 4 + i) * 65 + tx * 4 + j] = acc[i][j];
        for (int idx = t; idx < 4096; idx += 256) {
            int f = idx >> 6, d = idx & 63;
            int kf = k0 + f;
            float vr = 0.f, vi = 0.f;
            if (kf < FF) {
                size_t g = basebh + (size_t)kf * EE + d;
                vr = Vr[g]; vi = Vi[g];
            }
            sKr[f * 65 + d] = vr;
            sKi[f * 65 + d] = vi;
        }
        __syncthreads();

        // O += P @ V
#pragma unroll 4
        for (int k = 0; k < 64; k++) {
            float p[4], vr[4], vi[4];
#pragma unroll
            for (int i = 0; i < 4; i++) p[i] = sP[(ty * 4 + i) * 65 + k];
#pragma unroll
            for (int j = 0; j < 4; j++) { vr[j] = sKr[k * 65 + tx * 4 + j]; vi[j] = sKi[k * 65 + tx * 4 + j]; }
#pragma unroll
            for (int i = 0; i < 4; i++)
#pragma unroll
                for (int j = 0; j < 4; j++) {
                    oR[i][j] += p[i] * vr[j];
                    oI[i][j] += p[i] * vi[j];
                }
        }
        __syncthreads();   // before buffers are overwritten next iteration
    }

#pragma unroll
    for (int i = 0; i < 4; i++) {
        int qf = q0 + ty * 4 + i;
        if (qf < FF) {
            float inv = 1.0f / l_[i];
            size_t g = basebh + (size_t)qf * EE + tx * 4;
#pragma unroll
            for (int j = 0; j < 4; j++) {
                Outr[g + j] = oR[i][j] * inv;
                Outi[g + j] = oI[i][j] * inv;
            }
        }
    }
}

// ---------------- host launcher ----------------
extern "C" void kernel_launch(void* const* d_in, const int* in_sizes, int n_in,
                              void* d_out, int out_size)
{
    const float* x    = (const float*)d_in[0];
    const float* gam  = (const float*)d_in[1];
    const float* bet  = (const float*)d_in[2];
    const float* Wq_r = (const float*)d_in[3];
    const float* bq_r = (const float*)d_in[4];
    const float* Wq_i = (const float*)d_in[5];
    const float* bq_i = (const float*)d_in[6];
    const float* Wk_r = (const float*)d_in[7];
    const float* bk_r = (const float*)d_in[8];
    const float* Wk_i = (const float*)d_in[9];
    const float* bk_i = (const float*)d_in[10];
    const float* Wv_r = (const float*)d_in[11];
    const float* bv_r = (const float*)d_in[12];
    const float* Wv_i = (const float*)d_in[13];
    const float* bv_i = (const float*)d_in[14];
    const float* Wo   = (const float*)d_in[15];
    float* out = (float*)d_out;

    static int smem_set = 0;
    if (!smem_set) {
        cudaFuncSetAttribute(attn_kernel, cudaFuncAttributeMaxDynamicSharedMemorySize, ATTN_SMEM);
        smem_set = 1;
    }

    // device-global scratch addresses
    float *p_xn, *p_xt, *p_xr, *p_xi, *p_Qr, *p_Qi, *p_Kr, *p_Ki, *p_Vr, *p_Vi, *p_Or, *p_Oi, *p_y;
    cudaGetSymbolAddress((void**)&p_xn, g_xn);
    cudaGetSymbolAddress((void**)&p_xt, g_xt);
    cudaGetSymbolAddress((void**)&p_xr, g_xr);
    cudaGetSymbolAddress((void**)&p_xi, g_xi);
    cudaGetSymbolAddress((void**)&p_Qr, g_Qr);
    cudaGetSymbolAddress((void**)&p_Qi, g_Qi);
    cudaGetSymbolAddress((void**)&p_Kr, g_Kr);
    cudaGetSymbolAddress((void**)&p_Ki, g_Ki);
    cudaGetSymbolAddress((void**)&p_Vr, g_Vr);
    cudaGetSymbolAddress((void**)&p_Vi, g_Vi);
    cudaGetSymbolAddress((void**)&p_Or, g_Or);
    cudaGetSymbolAddress((void**)&p_Oi, g_Oi);
    cudaGetSymbolAddress((void**)&p_y,  g_y);

    const int MF = BB * FF;      // 8196 projection rows
    const int ML = BB * LL;      // 16384 output rows

    // 1) LayerNorm
    ln_kernel<<<BB * LL, 256>>>(x, gam, bet);

    // 2) transpose to [B][E][L] for coalesced FFT
    {
        dim3 g(EE / 32, LL / 32, BB), blk(32, 8);
        transpose_LE_to_EL<<<g, blk>>>();
    }

    // 3) rfft
    rfft_kernel<<<BB * EE, 256>>>();

    // 4) six projections
    {
        dim3 g((MF + 63) / 64, EE / 64);
        gemm_nt<<<g, 256>>>(p_xr, Wq_r, bq_r, p_Qr, MF);
        gemm_nt<<<g, 256>>>(p_xi, Wq_i, bq_i, p_Qi, MF);
        gemm_nt<<<g, 256>>>(p_xr, Wk_r, bk_r, p_Kr, MF);
        gemm_nt<<<g, 256>>>(p_xi, Wk_i, bk_i, p_Ki, MF);
        gemm_nt<<<g, 256>>>(p_xr, Wv_r, bv_r, p_Vr, MF);
        gemm_nt<<<g, 256>>>(p_xi, Wv_i, bv_i, p_Vi, MF);
    }

    // 5) attention
    {
        dim3 g((FF + 63) / 64, BB * HH);
        attn_kernel<<<g, 256, ATTN_SMEM>>>(p_Qr, p_Qi, p_Kr, p_Ki, p_Vr, p_Vi, p_Or, p_Oi);
    }

    // 6) irfft (writes g_xt as [B][E][L])
    irfft_kernel<<<BB * EE, 256>>>();

    // 7) transpose back to [B][L][E]
    {
        dim3 g(LL / 32, EE / 32, BB), blk(32, 8);
        transpose_EL_to_LE<<<g, blk>>>();
    }

    // 8) final projection: out = y @ Wo^T
    {
        dim3 g((ML + 63) / 64, EE / 64);
        gemm_nt<<<g, 256>>>(p_y, Wo, nullptr, out, ML);
    }
}

// round 8
// speedup vs baseline: 2.0336x; 2.0336x over previous
#include <cuda_runtime.h>
#include <math.h>

// ---------------- problem constants ----------------
#define BB 4
#define LL 4096
#define EE 512
#define FF 2049
#define HH 8
#define DD 64
#define FFTM 2048          // half-size complex FFT length

// ---------------- scratch (device globals; allocation-free) ----------------
__device__ float g_xn[BB * LL * EE];       // layernormed x       [B][L][E]
__device__ float g_xt[BB * EE * LL];       // transposed          [B][E][L] (reused for irfft output)
__device__ float g_xr[BB * FF * EE];       // rfft real           [B][F][E]
__device__ float g_xi[BB * FF * EE];       // rfft imag
__device__ float g_Qr[BB * FF * EE];
__device__ float g_Qi[BB * FF * EE];
__device__ float g_Kr[BB * FF * EE];
__device__ float g_Ki[BB * FF * EE];
__device__ float g_Vr[BB * FF * EE];
__device__ float g_Vi[BB * FF * EE];
__device__ float g_Or[BB * FF * EE];       // attention out real  [B][F][E]
__device__ float g_Oi[BB * FF * EE];
__device__ float g_y [BB * LL * EE];       // irfft result        [B][L][E]
__device__ float2 g_twS[1024];             // exp(-2*pi*i*p/2048)
__device__ float2 g_twP[FF];               // exp(-pi*i*k/2048)

// ---------------- tf32 helpers ----------------
__device__ __forceinline__ float tf32r(float x) {
    unsigned u;
    asm("cvt.rna.tf32.f32 %0, %1;" : "=r"(u) : "f"(x));
    return __uint_as_float(u);
}
__device__ __forceinline__ void mma8(float* c, const float* a, const float* b) {
    asm volatile(
        "mma.sync.aligned.m16n8k8.row.col.f32.tf32.tf32.f32 "
        "{%0,%1,%2,%3},{%4,%5,%6,%7},{%8,%9},{%0,%1,%2,%3};"
        : "+f"(c[0]), "+f"(c[1]), "+f"(c[2]), "+f"(c[3])
        : "r"(__float_as_uint(a[0])), "r"(__float_as_uint(a[1])),
          "r"(__float_as_uint(a[2])), "r"(__float_as_uint(a[3])),
          "r"(__float_as_uint(b[0])), "r"(__float_as_uint(b[1])));
}

// ---------------- twiddle table init ----------------
__global__ void twiddle_init()
{
    int t = blockIdx.x * 256 + threadIdx.x;
    if (t < 1024) {
        float sn, cs; sincospif(-(float)t * (1.0f / 1024.0f), &sn, &cs);
        g_twS[t] = make_float2(cs, sn);
    }
    if (t < FF) {
        float sn, cs; sincospif(-(float)t * (1.0f / 2048.0f), &sn, &cs);
        g_twP[t] = make_float2(cs, sn);
    }
}

// ---------------- LayerNorm ----------------
__global__ void ln_kernel(const float* __restrict__ x,
                          const float* __restrict__ gam,
                          const float* __restrict__ bet)
{
    __shared__ float sa[8], sb[8];
    int row = blockIdx.x;
    const float* xr = x + (size_t)row * EE;
    float* o = g_xn + (size_t)row * EE;
    int t = threadIdx.x;
    float v0 = xr[t], v1 = xr[t + 256];
    float s = v0 + v1, s2 = v0 * v0 + v1 * v1;
#pragma unroll
    for (int off = 16; off; off >>= 1) {
        s  += __shfl_xor_sync(0xffffffffu, s,  off);
        s2 += __shfl_xor_sync(0xffffffffu, s2, off);
    }
    if ((t & 31) == 0) { sa[t >> 5] = s; sb[t >> 5] = s2; }
    __syncthreads();
    s = 0.f; s2 = 0.f;
#pragma unroll
    for (int i = 0; i < 8; i++) { s += sa[i]; s2 += sb[i]; }
    float mean = s * (1.0f / EE);
    float var  = s2 * (1.0f / EE) - mean * mean;
    float rs   = rsqrtf(var + 1e-5f);
    o[t]       = (v0 - mean) * rs * gam[t]       + bet[t];
    o[t + 256] = (v1 - mean) * rs * gam[t + 256] + bet[t + 256];
}

// ---------------- transposes ----------------
__global__ void transpose_LE_to_EL()
{
    __shared__ float tile[32][33];
    int b  = blockIdx.z;
    int e0 = blockIdx.x * 32;
    int l0 = blockIdx.y * 32;
    const float* s = g_xn + ((size_t)b * LL + l0) * EE + e0;
    for (int rr = threadIdx.y; rr < 32; rr += 8)
        tile[rr][threadIdx.x] = s[(size_t)rr * EE + threadIdx.x];
    __syncthreads();
    float* d = g_xt + ((size_t)b * EE + e0) * LL + l0;
    for (int rr = threadIdx.y; rr < 32; rr += 8)
        d[(size_t)rr * LL + threadIdx.x] = tile[threadIdx.x][rr];
}

__global__ void transpose_EL_to_LE()
{
    __shared__ float tile[32][33];
    int b  = blockIdx.z;
    int l0 = blockIdx.x * 32;
    int e0 = blockIdx.y * 32;
    const float* s = g_xt + ((size_t)b * EE + e0) * LL + l0;
    for (int rr = threadIdx.y; rr < 32; rr += 8)
        tile[rr][threadIdx.x] = s[(size_t)rr * LL + threadIdx.x];
    __syncthreads();
    float* d = g_y + ((size_t)b * LL + l0) * EE + e0;
    for (int rr = threadIdx.y; rr < 32; rr += 8)
        d[(size_t)rr * EE + threadIdx.x] = tile[threadIdx.x][rr];
}

// ---------------- Stockham FFT (complex, length 2048, 256 threads) ----------------
__device__ __forceinline__ float2* fft_stockham2048(float2* src, float2* dst,
                                                    const float2* __restrict__ tw, int t)
{
#pragma unroll 1
    for (int stage = 0; stage < 11; stage++) {
        int s = 1 << stage;
#pragma unroll
        for (int i = 0; i < 4; i++) {
            int j = t + (i << 8);
            int p = j >> stage;
            int q = j & (s - 1);
            float2 u = src[q + (p << stage)];
            float2 v = src[q + ((p + (1024 >> stage)) << stage)];
            float2 ss = make_float2(u.x + v.x, u.y + v.y);
            float2 dd = make_float2(u.x - v.x, u.y - v.y);
            float2 w  = tw[p << stage];
            int od = q + (p << (stage + 1));
            dst[od]     = ss;
            dst[od + s] = make_float2(dd.x * w.x - dd.y * w.y,
                                      dd.x * w.y + dd.y * w.x);
        }
        __syncthreads();
        float2* tmp = src; src = dst; dst = tmp;
    }
    return src;
}

__global__ void rfft_kernel()
{
    __shared__ float2 bufA[FFTM], bufB[FFTM];
    __shared__ float2 tw[1024];
    int t  = threadIdx.x;
    int be = blockIdx.x;
    int b  = be >> 9, e = be & 511;

    const float2* src = (const float2*)(g_xt + (size_t)be * LL);
#pragma unroll
    for (int i = 0; i < 8; i++) bufA[t + (i << 8)] = src[t + (i << 8)];
#pragma unroll
    for (int i = 0; i < 4; i++) tw[t + (i << 8)] = g_twS[t + (i << 8)];
    __syncthreads();
    float2* Z = fft_stockham2048(bufA, bufB, tw, t);

    const float scale = 1.0f / 64.0f;
    for (int k = t; k <= FFTM; k += 256) {
        float2 zk = Z[k & (FFTM - 1)];
        float2 zm = Z[(FFTM - k) & (FFTM - 1)];
        float Er  = 0.5f * (zk.x + zm.x);
        float Eii = 0.5f * (zk.y - zm.y);
        float Or0 = 0.5f * (zk.x - zm.x);
        float Oi0 = 0.5f * (zk.y + zm.y);
        float2 w = g_twP[k];
        float ux = w.x * Or0 - w.y * Oi0;
        float uy = w.x * Oi0 + w.y * Or0;
        size_t g = ((size_t)b * FF + k) * EE + e;
        g_xr[g] = (Er  + uy) * scale;
        g_xi[g] = (Eii - ux) * scale;
    }
}

__global__ void irfft_kernel()
{
    __shared__ float2 bufA[FFTM], bufB[FFTM];
    __shared__ float2 tw[1024];
    int t  = threadIdx.x;
    int be = blockIdx.x;
    int b  = be >> 9, e = be & 511;

#pragma unroll
    for (int i = 0; i < 4; i++) {
        float2 w = g_twS[t + (i << 8)];
        tw[t + (i << 8)] = make_float2(w.x, -w.y);     // conj -> e^{+}
    }
    for (int k = t; k < FFTM; k += 256) {
        size_t gk = ((size_t)b * FF + k) * EE + e;
        size_t gm = ((size_t)b * FF + (FFTM - k)) * EE + e;
        float Xr_k = g_Or[gk];
        float Xi_k = (k == 0) ? 0.0f : g_Oi[gk];
        float Xr_m = g_Or[gm];
        float Xi_m = (k == 0) ? 0.0f : g_Oi[gm];
        float Er  = 0.5f * (Xr_k + Xr_m);
        float Ei  = 0.5f * (Xi_k - Xi_m);
        float Or0 = 0.5f * (Xr_k - Xr_m);
        float Oi0 = 0.5f * (Xi_k + Xi_m);
        float2 w = g_twP[k];                            // use conj
        float cs = w.x, sn = -w.y;
        float ux = cs * Or0 - sn * Oi0;
        float uy = cs * Oi0 + sn * Or0;
        bufA[k] = make_float2(Er - uy, Ei + ux);
    }
    __syncthreads();
    float2* w = fft_stockham2048(bufA, bufB, tw, t);

    float2* out = (float2*)(g_xt + (size_t)be * LL);
    const float sc = 1.0f / 32.0f;
#pragma unroll
    for (int i = 0; i < 8; i++) {
        int n = t + (i << 8);
        float2 z = w[n];
        out[n] = make_float2(z.x * sc, z.y * sc);
    }
}

// ---------------- tf32 tensor-core GEMM: C[M,512] = A * W^T (+bias) ----------------
// block tile 128m x 64n, k-stage 32.  8 warps: 4x2 grid of 32x32 warp tiles.
__global__ void __launch_bounds__(256) gemm_tc(const float* __restrict__ A,
                                               const float* __restrict__ W,
                                               const float* __restrict__ bias,
                                               float* __restrict__ C, int M)
{
    __shared__ float sA[128 * 36];
    __shared__ float sB[64 * 36];
    int m0 = blockIdx.x * 128, n0 = blockIdx.y * 64;
    int t = threadIdx.x, lane = t & 31, w = t >> 5;
    int g = lane >> 2, t4 = lane & 3;
    int wm = w >> 1, wn = w & 1;
    float acc[2][4][4] = {};

    for (int k0 = 0; k0 < 512; k0 += 32) {
#pragma unroll
        for (int i = 0; i < 4; i++) {
            int id = t + i * 256;
            int r = id >> 3, kq = (id & 7) * 4;
            float4 v = make_float4(0.f, 0.f, 0.f, 0.f);
            if (m0 + r < M) v = *(const float4*)&A[(size_t)(m0 + r) * 512 + k0 + kq];
            float* d = &sA[r * 36 + kq];
            d[0] = tf32r(v.x); d[1] = tf32r(v.y); d[2] = tf32r(v.z); d[3] = tf32r(v.w);
        }
#pragma unroll
        for (int i = 0; i < 2; i++) {
            int id = t + i * 256;
            int r = id >> 3, kq = (id & 7) * 4;
            float4 v = *(const float4*)&W[(size_t)(n0 + r) * 512 + k0 + kq];
            float* d = &sB[r * 36 + kq];
            d[0] = tf32r(v.x); d[1] = tf32r(v.y); d[2] = tf32r(v.z); d[3] = tf32r(v.w);
        }
        __syncthreads();
#pragma unroll
        for (int ks = 0; ks < 4; ks++) {
            int kk = ks * 8 + t4;
            float a[2][4];
#pragma unroll
            for (int mt = 0; mt < 2; mt++) {
                int row = wm * 32 + mt * 16 + g;
                a[mt][0] = sA[row * 36 + kk];
                a[mt][1] = sA[(row + 8) * 36 + kk];
                a[mt][2] = sA[row * 36 + kk + 4];
                a[mt][3] = sA[(row + 8) * 36 + kk + 4];
            }
#pragma unroll
            for (int nt = 0; nt < 4; nt++) {
                int col = wn * 32 + nt * 8 + g;
                float b[2] = { sB[col * 36 + kk], sB[col * 36 + kk + 4] };
                mma8(acc[0][nt], a[0], b);
                mma8(acc[1][nt], a[1], b);
            }
        }
        __syncthreads();
    }
#pragma unroll
    for (int nt = 0; nt < 4; nt++) {
        int col = n0 + wn * 32 + nt * 8 + 2 * t4;
        float b0 = bias ? bias[col] : 0.f;
        float b1 = bias ? bias[col + 1] : 0.f;
#pragma unroll
        for (int mt = 0; mt < 2; mt++) {
            int row = m0 + wm * 32 + mt * 16 + g;
            if (row < M) {
                float2 v = make_float2(acc[mt][nt][0] + b0, acc[mt][nt][1] + b1);
                *(float2*)&C[(size_t)row * 512 + col] = v;
            }
            if (row + 8 < M) {
                float2 v = make_float2(acc[mt][nt][2] + b0, acc[mt][nt][3] + b1);
                *(float2*)&C[(size_t)(row + 8) * 512 + col] = v;
            }
        }
    }
}

// ---------------- tf32 tensor-core flash attention ----------------
// block: 256 thr, one (b,h), q-tile 128, k-tile 64.
// warp grid 4m x 2n, warp tile 32x32 (both S and O phases).
#define SQ_LD 68
#define ATTN_FLOATS (2 * 128 * 68 + 2 * 64 * 68 + 128 * 68 + 3 * 128)
#define ATTN_SMEM (ATTN_FLOATS * 4)
__global__ void __launch_bounds__(256, 1) attn_tc(
    const float* __restrict__ Qr, const float* __restrict__ Qi,
    const float* __restrict__ Kr, const float* __restrict__ Ki,
    const float* __restrict__ Vr, const float* __restrict__ Vi,
    float* __restrict__ Outr, float* __restrict__ Outi)
{
    extern __shared__ float sm[];
    float* sQr = sm;                        // [128][68]
    float* sQi = sQr + 128 * SQ_LD;
    float* sKr = sQi + 128 * SQ_LD;         // [64][68]  K, then V^T [d][f]
    float* sKi = sKr + 64 * SQ_LD;
    float* sS  = sKi + 64 * SQ_LD;          // [128][68] S then P
    float* sMm = sS + 128 * SQ_LD;
    float* sLl = sMm + 128;
    float* sAl = sLl + 128;

    int bh = blockIdx.y;
    int b = bh >> 3, h = bh & 7;
    int q0 = blockIdx.x * 128;
    int t = threadIdx.x, lane = t & 31, w = t >> 5;
    int g = lane >> 2, t4 = lane & 3;
    int wm = w >> 1, wn = w & 1;
    const size_t base = (size_t)b * FF * EE + h * DD;

    // init stats + load Q (scaled)
    if (t < 128) { sMm[t] = -1e30f; sLl[t] = 0.f; }
    for (int idx = t; idx < 8192; idx += 256) {
        int q = idx >> 6, d = idx & 63;
        int gq = q0 + q;
        float vr = 0.f, vi = 0.f;
        if (gq < FF) {
            size_t gg = base + (size_t)gq * EE + d;
            vr = Qr[gg] * 0.125f; vi = Qi[gg] * 0.125f;
        }
        sQr[q * SQ_LD + d] = tf32r(vr);
        sQi[q * SQ_LD + d] = tf32r(vi);
    }

    float accR[2][4][4] = {}, accI[2][4][4] = {};

    for (int f0 = 0; f0 < 2112; f0 += 64) {
        __syncthreads();
        // load K tile [f][d]
        for (int idx = t; idx < 4096; idx += 256) {
            int f = idx >> 6, d = idx & 63;
            int gf = f0 + f;
            float vr = 0.f, vi = 0.f;
            if (gf < FF) {
                size_t gg = base + (size_t)gf * EE + d;
                vr = Kr[gg]; vi = Ki[gg];
            }
            sKr[f * SQ_LD + d] = tf32r(vr);
            sKi[f * SQ_LD + d] = tf32r(vi);
        }
        __syncthreads();

        // S = Qr Kr^T + Qi Ki^T
        float sacc[2][4][4] = {};
#pragma unroll
        for (int ks = 0; ks < 8; ks++) {
            int kk = ks * 8 + t4;
            float a[2][4];
#pragma unroll
            for (int mt = 0; mt < 2; mt++) {
                int row = wm * 32 + mt * 16 + g;
                a[mt][0] = sQr[row * SQ_LD + kk];
                a[mt][1] = sQr[(row + 8) * SQ_LD + kk];
                a[mt][2] = sQr[row * SQ_LD + kk + 4];
                a[mt][3] = sQr[(row + 8) * SQ_LD + kk + 4];
            }
#pragma unroll
            for (int nt = 0; nt < 4; nt++) {
                int f = wn * 32 + nt * 8 + g;
                float bfr[2] = { sKr[f * SQ_LD + kk], sKr[f * SQ_LD + kk + 4] };
                mma8(sacc[0][nt], a[0], bfr);
                mma8(sacc[1][nt], a[1], bfr);
            }
        }
#pragma unroll
        for (int ks = 0; ks < 8; ks++) {
            int kk = ks * 8 + t4;
            float a[2][4];
#pragma unroll
            for (int mt = 0; mt < 2; mt++) {
                int row = wm * 32 + mt * 16 + g;
                a[mt][0] = sQi[row * SQ_LD + kk];
                a[mt][1] = sQi[(row + 8) * SQ_LD + kk];
                a[mt][2] = sQi[row * SQ_LD + kk + 4];
                a[mt][3] = sQi[(row + 8) * SQ_LD + kk + 4];
            }
#pragma unroll
            for (int nt = 0; nt < 4; nt++) {
                int f = wn * 32 + nt * 8 + g;
                float bfi[2] = { sKi[f * SQ_LD + kk], sKi[f * SQ_LD + kk + 4] };
                mma8(sacc[0][nt], a[0], bfi);
                mma8(sacc[1][nt], a[1], bfi);
            }
        }
        // write S
#pragma unroll
        for (int mt = 0; mt < 2; mt++) {
            int row = wm * 32 + mt * 16 + g;
#pragma unroll
            for (int nt = 0; nt < 4; nt++) {
                int col = wn * 32 + nt * 8 + 2 * t4;
                *(float2*)&sS[row * SQ_LD + col]       = make_float2(sacc[mt][nt][0], sacc[mt][nt][1]);
                *(float2*)&sS[(row + 8) * SQ_LD + col] = make_float2(sacc[mt][nt][2], sacc[mt][nt][3]);
            }
        }
        __syncthreads();

        // softmax: 2 threads per row, 32 cols each
        {
            int r = t >> 1, c0 = (t & 1) * 32;
            float4 v[8];
            float mx = -1e30f;
#pragma unroll
            for (int j = 0; j < 8; j++) {
                v[j] = *(float4*)&sS[r * SQ_LD + c0 + j * 4];
                int cb = f0 + c0 + j * 4;
                if (cb + 0 < FF) mx = fmaxf(mx, v[j].x);
                if (cb + 1 < FF) mx = fmaxf(mx, v[j].y);
                if (cb + 2 < FF) mx = fmaxf(mx, v[j].z);
                if (cb + 3 < FF) mx = fmaxf(mx, v[j].w);
            }
            mx = fmaxf(mx, __shfl_xor_sync(0xffffffffu, mx, 1));
            float mold = sMm[r];
            float mnew = fmaxf(mold, mx);
            float al = __expf(mold - mnew);
            float sum = 0.f;
#pragma unroll
            for (int j = 0; j < 8; j++) {
                int cb = f0 + c0 + j * 4;
                float p0 = (cb + 0 < FF) ? __expf(v[j].x - mnew) : 0.f;
                float p1 = (cb + 1 < FF) ? __expf(v[j].y - mnew) : 0.f;
                float p2 = (cb + 2 < FF) ? __expf(v[j].z - mnew) : 0.f;
                float p3 = (cb + 3 < FF) ? __expf(v[j].w - mnew) : 0.f;
                sum += p0 + p1 + p2 + p3;
                v[j] = make_float4(tf32r(p0), tf32r(p1), tf32r(p2), tf32r(p3));
            }
            sum += __shfl_xor_sync(0xffffffffu, sum, 1);
            if ((t & 1) == 0) {
                sMm[r] = mnew;
                sLl[r] = sLl[r] * al + sum;
                sAl[r] = al;
            }
#pragma unroll
            for (int j = 0; j < 8; j++)
                *(float4*)&sS[r * SQ_LD + c0 + j * 4] = v[j];
        }
        __syncthreads();

        // rescale O accumulators
#pragma unroll
        for (int mt = 0; mt < 2; mt++) {
            int row = wm * 32 + mt * 16 + g;
            float a0 = sAl[row], a1 = sAl[row + 8];
#pragma unroll
            for (int nt = 0; nt < 4; nt++) {
                accR[mt][nt][0] *= a0; accR[mt][nt][1] *= a0;
                accR[mt][nt][2] *= a1; accR[mt][nt][3] *= a1;
                accI[mt][nt][0] *= a0; accI[mt][nt][1] *= a0;
                accI[mt][nt][2] *= a1; accI[mt][nt][3] *= a1;
            }
        }
        // load V transposed [d][f] into K buffers
        for (int idx = t; idx < 4096; idx += 256) {
            int f = idx >> 6, d = idx & 63;
            int gf = f0 + f;
            float vr = 0.f, vi = 0.f;
            if (gf < FF) {
                size_t gg = base + (size_t)gf * EE + d;
                vr = Vr[gg]; vi = Vi[gg];
            }
            sKr[d * SQ_LD + f] = tf32r(vr);
            sKi[d * SQ_LD + f] = tf32r(vi);
        }
        __syncthreads();

        // O += P @ V  (r and i)
#pragma unroll
        for (int ks = 0; ks < 8; ks++) {
            int kk = ks * 8 + t4;
            float a[2][4];
#pragma unroll
            for (int mt = 0; mt < 2; mt++) {
                int row = wm * 32 + mt * 16 + g;
                a[mt][0] = sS[row * SQ_LD + kk];
                a[mt][1] = sS[(row + 8) * SQ_LD + kk];
                a[mt][2] = sS[row * SQ_LD + kk + 4];
                a[mt][3] = sS[(row + 8) * SQ_LD + kk + 4];
            }
#pragma unroll
            for (int nt = 0; nt < 4; nt++) {
                int d = wn * 32 + nt * 8 + g;
                float br[2] = { sKr[d * SQ_LD + kk], sKr[d * SQ_LD + kk + 4] };
                mma8(accR[0][nt], a[0], br);
                mma8(accR[1][nt], a[1], br);
                float bi[2] = { sKi[d * SQ_LD + kk], sKi[d * SQ_LD + kk + 4] };
                mma8(accI[0][nt], a[0], bi);
                mma8(accI[1][nt], a[1], bi);
            }
        }
    }
    __syncthreads();

    // write output (divide by l)
#pragma unroll
    for (int mt = 0; mt < 2; mt++) {
        int row = wm * 32 + mt * 16 + g;
        float li0 = 1.0f / sLl[row];
        float li1 = 1.0f / sLl[row + 8];
        int q  = q0 + row;
#pragma unroll
        for (int nt = 0; nt < 4; nt++) {
            int col = wn * 32 + nt * 8 + 2 * t4;
            if (q < FF) {
                size_t gg = base + (size_t)q * EE + col;
                *(float2*)&Outr[gg] = make_float2(accR[mt][nt][0] * li0, accR[mt][nt][1] * li0);
                *(float2*)&Outi[gg] = make_float2(accI[mt][nt][0] * li0, accI[mt][nt][1] * li0);
            }
            if (q + 8 < FF) {
                size_t gg = base + (size_t)(q + 8) * EE + col;
                *(float2*)&Outr[gg] = make_float2(accR[mt][nt][2] * li1, accR[mt][nt][3] * li1);
                *(float2*)&Outi[gg] = make_float2(accI[mt][nt][2] * li1, accI[mt][nt][3] * li1);
            }
        }
    }
}

// ---------------- host launcher ----------------
extern "C" void kernel_launch(void* const* d_in, const int* in_sizes, int n_in,
                              void* d_out, int out_size)
{
    const float* x    = (const float*)d_in[0];
    const float* gam  = (const float*)d_in[1];
    const float* bet  = (const float*)d_in[2];
    const float* Wq_r = (const float*)d_in[3];
    const float* bq_r = (const float*)d_in[4];
    const float* Wq_i = (const float*)d_in[5];
    const float* bq_i = (const float*)d_in[6];
    const float* Wk_r = (const float*)d_in[7];
    const float* bk_r = (const float*)d_in[8];
    const float* Wk_i = (const float*)d_in[9];
    const float* bk_i = (const float*)d_in[10];
    const float* Wv_r = (const float*)d_in[11];
    const float* bv_r = (const float*)d_in[12];
    const float* Wv_i = (const float*)d_in[13];
    const float* bv_i = (const float*)d_in[14];
    const float* Wo   = (const float*)d_in[15];
    float* out = (float*)d_out;

    static int smem_set = 0;
    if (!smem_set) {
        cudaFuncSetAttribute(attn_tc, cudaFuncAttributeMaxDynamicSharedMemorySize, ATTN_SMEM);
        smem_set = 1;
    }

    float *p_xr, *p_xi, *p_Qr, *p_Qi, *p_Kr, *p_Ki, *p_Vr, *p_Vi, *p_Or, *p_Oi, *p_y;
    cudaGetSymbolAddress((void**)&p_xr, g_xr);
    cudaGetSymbolAddress((void**)&p_xi, g_xi);
    cudaGetSymbolAddress((void**)&p_Qr, g_Qr);
    cudaGetSymbolAddress((void**)&p_Qi, g_Qi);
    cudaGetSymbolAddress((void**)&p_Kr, g_Kr);
    cudaGetSymbolAddress((void**)&p_Ki, g_Ki);
    cudaGetSymbolAddress((void**)&p_Vr, g_Vr);
    cudaGetSymbolAddress((void**)&p_Vi, g_Vi);
    cudaGetSymbolAddress((void**)&p_Or, g_Or);
    cudaGetSymbolAddress((void**)&p_Oi, g_Oi);
    cudaGetSymbolAddress((void**)&p_y,  g_y);

    const int MF = BB * FF;      // 8196
    const int ML = BB * LL;      // 16384

    twiddle_init<<<9, 256>>>();
    ln_kernel<<<BB * LL, 256>>>(x, gam, bet);
    {
        dim3 g(EE / 32, LL / 32, BB), blk(32, 8);
        transpose_LE_to_EL<<<g, blk>>>();
    }
    rfft_kernel<<<BB * EE, 256>>>();
    {
        dim3 g((MF + 127) / 128, 8);
        gemm_tc<<<g, 256>>>(p_xr, Wq_r, bq_r, p_Qr, MF);
        gemm_tc<<<g, 256>>>(p_xi, Wq_i, bq_i, p_Qi, MF);
        gemm_tc<<<g, 256>>>(p_xr, Wk_r, bk_r, p_Kr, MF);
        gemm_tc<<<g, 256>>>(p_xi, Wk_i, bk_i, p_Ki, MF);
        gemm_tc<<<g, 256>>>(p_xr, Wv_r, bv_r, p_Vr, MF);
        gemm_tc<<<g, 256>>>(p_xi, Wv_i, bv_i, p_Vi, MF);
    }
    {
        dim3 g((FF + 127) / 128, BB * HH);
        attn_tc<<<g, 256, ATTN_SMEM>>>(p_Qr, p_Qi, p_Kr, p_Ki, p_Vr, p_Vi, p_Or, p_Oi);
    }
    irfft_kernel<<<BB * EE, 256>>>();
    {
        dim3 g(LL / 32, EE / 32, BB), blk(32, 8);
        transpose_EL_to_LE<<<g, blk>>>();
    }
    {
        dim3 g((ML + 127) / 128, 8);
        gemm_tc<<<g, 256>>>(p_y, Wo, nullptr, out, ML);
    }
}